// round 2
// baseline (speedup 1.0000x reference)
#include <cuda_runtime.h>
#include <cstdint>

// ---------------- constants ----------------
#define Bn 32
#define Mn 448
#define Cn 384
#define Sn 512
#define SDn 128
#define Kn 8
// rows of the "graph" tensor, flattened (b*512 + i)
#define NROWS (Bn * Sn)   // 16384

// ---------------- scratch (__device__ globals; no allocation) ----------------
__device__ int      g_idx[NROWS * Kn];          // knn indices (local per batch)
__device__ float    g_X[NROWS * 128];           // [row][0:64]=h1(relu), [64:128]=agg1
__device__ unsigned g_proxy[Bn * SDn];          // encoded float max
__device__ float    g_g2qc[Bn * 1408];          // [0:1024]=g2, [1024:1408]=qc
__device__ float    g_g1[Bn * 1024];
__device__ float    g_partial[Bn * 11 * Cn];    // base partial sums over 11 k-chunks

// ---------------- helpers ----------------
__device__ __forceinline__ unsigned fenc(float f) {
    unsigned u = __float_as_uint(f);
    return (u & 0x80000000u) ? ~u : (u | 0x80000000u);
}
__device__ __forceinline__ float fdec(unsigned e) {
    unsigned u = (e & 0x80000000u) ? (e ^ 0x80000000u) : ~e;
    return __uint_as_float(u);
}
__device__ __forceinline__ float warp_sum(float v) {
    #pragma unroll
    for (int off = 16; off; off >>= 1) v += __shfl_down_sync(0xffffffffu, v, off);
    return v;
}

// ---------------- K0: knn (one block per batch) + proxy init ----------------
__global__ void knn_kernel(const float* __restrict__ skel) {
    int b = blockIdx.x;
    int i = threadIdx.x; // 0..511
    __shared__ float sx[Sn], sy[Sn], sz[Sn];
    const float* sk = skel + (size_t)b * Sn * 3;
    sx[i] = sk[i * 3 + 0];
    sy[i] = sk[i * 3 + 1];
    sz[i] = sk[i * 3 + 2];
    if (i < SDn) g_proxy[b * SDn + i] = 0u; // "-inf" key
    __syncthreads();

    float xi = sx[i], yi = sy[i], zi = sz[i];
    float bd[Kn]; int bi[Kn];
    #pragma unroll
    for (int k = 0; k < Kn; k++) { bd[k] = 3.0e38f; bi[k] = 0; }

    for (int j = 0; j < Sn; j++) {
        if (j == i) continue;
        float dx = xi - sx[j], dy = yi - sy[j], dz = zi - sz[j];
        float d = dx * dx + dy * dy + dz * dz;
        if (d < bd[Kn - 1]) {
            float cd = d; int ci = j;
            #pragma unroll
            for (int k = 0; k < Kn; k++) {
                if (cd < bd[k]) {
                    float td = bd[k]; int ti = bi[k];
                    bd[k] = cd; bi[k] = ci;
                    cd = td; ci = ti;
                }
            }
        }
    }
    int row = b * Sn + i;
    #pragma unroll
    for (int k = 0; k < Kn; k++) g_idx[row * Kn + k] = bi[k];
}

// ---------------- K1: graph conv 1 (3 -> 64) + relu, writes X[:, :64] ----------------
__global__ void gc1_kernel(const float* __restrict__ skel,
                           const float* __restrict__ wroot,
                           const float* __restrict__ wrel,
                           const float* __restrict__ bias) {
    int gid = blockIdx.x * blockDim.x + threadIdx.x;
    if (gid >= NROWS * 64) return;
    int c = gid & 63;
    int row = gid >> 6;
    int b = row >> 9;
    int i = row & 511;
    const float* sk = skel + (size_t)b * Sn * 3;
    float x0 = sk[i * 3 + 0], x1 = sk[i * 3 + 1], x2 = sk[i * 3 + 2];
    float a0 = 0.f, a1 = 0.f, a2 = 0.f;
    const int* id = g_idx + row * Kn;
    #pragma unroll
    for (int k = 0; k < Kn; k++) {
        int j = id[k];
        a0 += sk[j * 3 + 0];
        a1 += sk[j * 3 + 1];
        a2 += sk[j * 3 + 2];
    }
    float h = bias[c];
    h = fmaf(x0, wroot[0 * 64 + c], h);
    h = fmaf(x1, wroot[1 * 64 + c], h);
    h = fmaf(x2, wroot[2 * 64 + c], h);
    h = fmaf(a0, wrel[0 * 64 + c], h);
    h = fmaf(a1, wrel[1 * 64 + c], h);
    h = fmaf(a2, wrel[2 * 64 + c], h);
    g_X[(size_t)row * 128 + c] = fmaxf(h, 0.f);
}

// ---------------- K2: neighbor aggregation of h1, writes X[:, 64:128] ----------------
__global__ void agg_kernel() {
    int gid = blockIdx.x * blockDim.x + threadIdx.x;
    if (gid >= NROWS * 64) return;
    int c = gid & 63;
    int row = gid >> 6;
    int base = (row >> 9) << 9; // b*512
    const int* id = g_idx + row * Kn;
    float s = 0.f;
    #pragma unroll
    for (int k = 0; k < Kn; k++) s += g_X[(size_t)(base + id[k]) * 128 + c];
    g_X[(size_t)row * 128 + 64 + c] = s;
}

// ---------------- K3: gc2 GEMM (16384x128 @ 128x128) fused with column max -> proxy ----------------
// h2 = h1 @ wroot2 + agg1 @ wrel2 + b2 ; proxy[b] = max over the 512 rows of batch b
__global__ __launch_bounds__(256) void gc2_kernel(const float* __restrict__ wroot2,
                                                  const float* __restrict__ wrel2,
                                                  const float* __restrict__ b2) {
    __shared__ float Xs[64 * 68]; // [k][row], padded
    __shared__ float Ws[64 * 64]; // [k][col]
    int n0 = blockIdx.x * 64;     // 0 or 64
    int r0 = blockIdx.y * 64;     // row tile (within one batch: 64 | 512)
    int tid = threadIdx.x;
    int tr = tid >> 4;            // 0..15 -> 4 rows each
    int tc = tid & 15;            // 0..15 -> 4 cols each

    float acc[4][4];
    #pragma unroll
    for (int i = 0; i < 4; i++)
        #pragma unroll
        for (int j = 0; j < 4; j++) acc[i][j] = 0.f;

    for (int kc = 0; kc < 2; kc++) {
        const float* W = kc ? wrel2 : wroot2; // (64,128) row-major
        #pragma unroll
        for (int it = 0; it < 4; it++) {
            int lin = it * 256 + tid;  // 0..1023 (float4 units)
            int r = lin >> 4;          // 0..63
            int k4 = lin & 15;         // 0..15
            float4 v = *(const float4*)(g_X + (size_t)(r0 + r) * 128 + kc * 64 + k4 * 4);
            Xs[(k4 * 4 + 0) * 68 + r] = v.x;
            Xs[(k4 * 4 + 1) * 68 + r] = v.y;
            Xs[(k4 * 4 + 2) * 68 + r] = v.z;
            Xs[(k4 * 4 + 3) * 68 + r] = v.w;
            float4 wv = *(const float4*)(W + (size_t)r * 128 + n0 + k4 * 4);
            *(float4*)(Ws + r * 64 + k4 * 4) = wv;
        }
        __syncthreads();
        #pragma unroll
        for (int k = 0; k < 64; k++) {
            float4 a = *(const float4*)(Xs + k * 68 + tr * 4);
            float4 w = *(const float4*)(Ws + k * 64 + tc * 4);
            float av[4] = {a.x, a.y, a.z, a.w};
            float wv[4] = {w.x, w.y, w.z, w.w};
            #pragma unroll
            for (int i = 0; i < 4; i++)
                #pragma unroll
                for (int j = 0; j < 4; j++)
                    acc[i][j] = fmaf(av[i], wv[j], acc[i][j]);
        }
        __syncthreads();
    }

    // per-thread column max over its 4 rows, then block reduce over 16 thread-rows
    float* sred = Xs;
    #pragma unroll
    for (int j = 0; j < 4; j++) {
        float m = fmaxf(fmaxf(acc[0][j], acc[1][j]), fmaxf(acc[2][j], acc[3][j]));
        sred[tr * 64 + tc * 4 + j] = m;
    }
    __syncthreads();
    if (tid < 64) {
        float m = sred[tid];
        #pragma unroll
        for (int t = 1; t < 16; t++) m = fmaxf(m, sred[t * 64 + tid]);
        m += b2[n0 + tid]; // max(acc)+bias == max(acc+bias)
        int b = r0 >> 9;
        atomicMax(&g_proxy[b * SDn + n0 + tid], fenc(m));
    }
}

// ---------------- K4: per-batch chain: proxy->kv->vh(=ctx)->qc ----------------
__global__ void chain1_kernel(const float* __restrict__ proj_w, const float* __restrict__ proj_b,
                              const float* __restrict__ attn_in_w, const float* __restrict__ attn_in_b,
                              const float* __restrict__ attn_out_w, const float* __restrict__ attn_out_b) {
    int b = blockIdx.x;
    int tid = threadIdx.x; // 384
    __shared__ float sp[SDn], skv[Cn], svh[Cn];
    if (tid < SDn) sp[tid] = fdec(g_proxy[b * SDn + tid]);
    __syncthreads();

    // kv = proxy @ proj_w + proj_b    (proj_w: (128,384) row-major; coalesced over c)
    float acc = proj_b[tid];
    #pragma unroll 8
    for (int k = 0; k < SDn; k++) acc = fmaf(sp[k], proj_w[k * Cn + tid], acc);
    skv[tid] = acc;
    __syncthreads();

    int w = tid >> 5, l = tid & 31; // 12 warps

    // vh = kv @ wv.T + bv (wv = attn_in_w rows [2C, 3C)); warp-per-output
    for (int t = 0; t < 32; t++) {
        int c = w * 32 + t;
        const float* row = attn_in_w + (size_t)(2 * Cn + c) * Cn;
        float p = 0.f;
        #pragma unroll
        for (int j = l; j < Cn; j += 32) p = fmaf(skv[j], row[j], p);
        p = warp_sum(p);
        if (l == 0) svh[c] = p + attn_in_b[2 * Cn + c];
    }
    __syncthreads();

    // qc = ctx @ attn_out_w.T + attn_out_b  (ctx == vh)
    for (int t = 0; t < 32; t++) {
        int c = w * 32 + t;
        const float* row = attn_out_w + (size_t)c * Cn;
        float p = 0.f;
        #pragma unroll
        for (int j = l; j < Cn; j += 32) p = fmaf(svh[j], row[j], p);
        p = warp_sum(p);
        if (l == 0) g_g2qc[b * 1408 + 1024 + c] = p + attn_out_b[c];
    }
}

// ---------------- K5: g1 = leaky(BN(qc @ inc1_w.T + inc1_b)) ----------------
__global__ void g1_kernel(const float* __restrict__ inc1_w, const float* __restrict__ inc1_b,
                          const float* __restrict__ bn_g, const float* __restrict__ bn_b,
                          const float* __restrict__ bn_m, const float* __restrict__ bn_v) {
    int b = blockIdx.x, ch = blockIdx.y; // 8 chunks of 128 outputs
    int tid = threadIdx.x;               // 256 = 8 warps
    __shared__ float sq[Cn];
    for (int i = tid; i < Cn; i += 256) sq[i] = g_g2qc[b * 1408 + 1024 + i];
    __syncthreads();
    int w = tid >> 5, l = tid & 31;
    for (int t = 0; t < 16; t++) {
        int o = ch * 128 + w * 16 + t;
        const float* row = inc1_w + (size_t)o * Cn;
        float p = 0.f;
        #pragma unroll
        for (int j = l; j < Cn; j += 32) p = fmaf(sq[j], row[j], p);
        p = warp_sum(p);
        if (l == 0) {
            float v = p + inc1_b[o];
            v = fmaf(bn_g[o] * (v - bn_m[o]), rsqrtf(bn_v[o] + 1e-5f), bn_b[o]);
            g_g1[b * 1024 + o] = (v >= 0.f) ? v : 0.2f * v;
        }
    }
}

// ---------------- K6: g2 = g1 @ inc2_w.T + inc2_b ----------------
__global__ void g2_kernel(const float* __restrict__ inc2_w, const float* __restrict__ inc2_b) {
    int b = blockIdx.x, ch = blockIdx.y;
    int tid = threadIdx.x; // 256
    __shared__ float sq[1024];
    for (int i = tid; i < 1024; i += 256) sq[i] = g_g1[b * 1024 + i];
    __syncthreads();
    int w = tid >> 5, l = tid & 31;
    for (int t = 0; t < 16; t++) {
        int o = ch * 128 + w * 16 + t;
        const float* row = inc2_w + (size_t)o * 1024;
        float p = 0.f;
        #pragma unroll 8
        for (int j = l; j < 1024; j += 32) p = fmaf(sq[j], row[j], p);
        p = warp_sum(p);
        if (l == 0) g_g2qc[b * 1408 + o] = p + inc2_b[o];
    }
}

// ---------------- K7: base partials: partial[b][ch] = g2qc[b][ch*128:+128] @ red_w rows ----------------
__global__ void base_partial_kernel(const float* __restrict__ red_w) {
    int b = blockIdx.x, ch = blockIdx.y; // 11 chunks of 128 rows (1408 total)
    int c = threadIdx.x;                 // 384
    __shared__ float sv[128];
    int o0 = ch * 128;
    if (c < 128) sv[c] = g_g2qc[b * 1408 + o0 + c];
    __syncthreads();
    float acc = 0.f;
    const float* wp = red_w + (size_t)o0 * Cn + c;
    #pragma unroll 8
    for (int r = 0; r < 128; r++) acc = fmaf(sv[r], wp[(size_t)r * Cn], acc);
    g_partial[(b * 11 + ch) * Cn + c] = acc;
}

// ---------------- K8: out[b,m,c] = red_b + sum(partials) + coarse[b,m]·red_w[1408:1411] ----------------
__global__ void out_kernel(const float* __restrict__ red_w, const float* __restrict__ red_b,
                           const float* __restrict__ coarse, float* __restrict__ out) {
    int gid = blockIdx.x * blockDim.x + threadIdx.x;
    if (gid >= Bn * Mn * (Cn / 4)) return;
    int qd = gid % (Cn / 4);
    int bm = gid / (Cn / 4);
    int b = bm / Mn;
    int c = qd * 4;

    float4 acc = *(const float4*)(red_b + c);
    #pragma unroll
    for (int ch = 0; ch < 11; ch++) {
        float4 p = *(const float4*)(g_partial + (b * 11 + ch) * Cn + c);
        acc.x += p.x; acc.y += p.y; acc.z += p.z; acc.w += p.w;
    }
    float c0 = coarse[bm * 3 + 0];
    float c1 = coarse[bm * 3 + 1];
    float c2 = coarse[bm * 3 + 2];
    float4 w0 = *(const float4*)(red_w + (size_t)1408 * Cn + c);
    float4 w1 = *(const float4*)(red_w + (size_t)1409 * Cn + c);
    float4 w2 = *(const float4*)(red_w + (size_t)1410 * Cn + c);
    acc.x += c0 * w0.x + c1 * w1.x + c2 * w2.x;
    acc.y += c0 * w0.y + c1 * w1.y + c2 * w2.y;
    acc.z += c0 * w0.z + c1 * w1.z + c2 * w2.z;
    acc.w += c0 * w0.w + c1 * w1.w + c2 * w2.w;
    *(float4*)(out + (size_t)bm * Cn + c) = acc;
}

// ---------------- launch ----------------
extern "C" void kernel_launch(void* const* d_in, const int* in_sizes, int n_in,
                              void* d_out, int out_size) {
    (void)in_sizes; (void)n_in; (void)out_size;
    const float* coarse     = (const float*)d_in[1];
    const float* skeleton   = (const float*)d_in[2];
    const float* gc1_wroot  = (const float*)d_in[3];
    const float* gc1_wrel   = (const float*)d_in[4];
    const float* gc1_b      = (const float*)d_in[5];
    const float* gc2_wroot  = (const float*)d_in[6];
    const float* gc2_wrel   = (const float*)d_in[7];
    const float* gc2_b      = (const float*)d_in[8];
    const float* proj_w     = (const float*)d_in[9];
    const float* proj_b     = (const float*)d_in[10];
    const float* attn_in_w  = (const float*)d_in[11];
    const float* attn_in_b  = (const float*)d_in[12];
    const float* attn_out_w = (const float*)d_in[13];
    const float* attn_out_b = (const float*)d_in[14];
    const float* inc1_w     = (const float*)d_in[15];
    const float* inc1_b     = (const float*)d_in[16];
    const float* bn_g       = (const float*)d_in[17];
    const float* bn_b       = (const float*)d_in[18];
    const float* bn_m       = (const float*)d_in[19];
    const float* bn_v       = (const float*)d_in[20];
    const float* inc2_w     = (const float*)d_in[21];
    const float* inc2_b     = (const float*)d_in[22];
    const float* red_w      = (const float*)d_in[23];
    const float* red_b      = (const float*)d_in[24];
    float* out = (float*)d_out;

    knn_kernel<<<Bn, Sn>>>(skeleton);
    gc1_kernel<<<(NROWS * 64) / 256, 256>>>(skeleton, gc1_wroot, gc1_wrel, gc1_b);
    agg_kernel<<<(NROWS * 64) / 256, 256>>>();
    gc2_kernel<<<dim3(2, NROWS / 64), 256>>>(gc2_wroot, gc2_wrel, gc2_b);
    chain1_kernel<<<Bn, Cn>>>(proj_w, proj_b, attn_in_w, attn_in_b, attn_out_w, attn_out_b);
    g1_kernel<<<dim3(Bn, 8), 256>>>(inc1_w, inc1_b, bn_g, bn_b, bn_m, bn_v);
    g2_kernel<<<dim3(Bn, 8), 256>>>(inc2_w, inc2_b);
    base_partial_kernel<<<dim3(Bn, 11), Cn>>>(red_w);
    out_kernel<<<(Bn * Mn * (Cn / 4) + 255) / 256, 256>>>(red_w, red_b, coarse, out);
}